// round 5
// baseline (speedup 1.0000x reference)
#include <cuda_runtime.h>
#include <cstdint>

#define BB 16
#define NN 10000
#define HH 128
#define EE 320000
#define MM (BB * NN)   // 160000 rows
#define DPAD 128       // padded max degree (mean 32, 11+ sigma headroom)

__device__ int g_cur[NN];
__device__ int g_colbuf[NN * DPAD];   // 5.1 MB padded buckets

// ---------------- helpers ----------------

__device__ __forceinline__ uint32_t f2tf32(float x) {
    uint32_t u;
    asm("cvt.rna.tf32.f32 %0, %1;" : "=r"(u) : "f"(x));
    return u;
}

__device__ __forceinline__ void mma_tf32(float* d, uint32_t a0, uint32_t a1,
                                         uint32_t a2, uint32_t a3,
                                         uint32_t b0, uint32_t b1) {
    asm volatile(
        "mma.sync.aligned.m16n8k8.row.col.f32.tf32.tf32.f32 "
        "{%0,%1,%2,%3}, {%4,%5,%6,%7}, {%8,%9}, {%0,%1,%2,%3};"
        : "+f"(d[0]), "+f"(d[1]), "+f"(d[2]), "+f"(d[3])
        : "r"(a0), "r"(a1), "r"(a2), "r"(a3), "r"(b0), "r"(b1));
}

// ---------------- bucket build ----------------

__global__ void k_zero() {
    int i = blockIdx.x * blockDim.x + threadIdx.x;
    if (i < NN) g_cur[i] = 0;
}

__global__ void k_fill(const int* __restrict__ src, const int* __restrict__ dst) {
    int e = blockIdx.x * blockDim.x + threadIdx.x;
    if (e < EE) {
        int d = dst[e];
        int p = atomicAdd(&g_cur[d], 1);
        if (p < DPAD) g_colbuf[d * DPAD + p] = src[e];
    }
}

// ---------------- Mega kernel: gather + 2-layer MLP + mask select ----------------
// Block: 128 rows x 128 cols, 256 threads = 8 warps (4m x 2n), warp tile 32x64.
// Dynamic smem (floats):
//   Ws : 32 x 132  @ 0      (4224)  — weight chunk (tf32), all phases
//   AH : 128 x 132 @ 4224   (16896) — gather result (phase 1 A, k 0..127),
//                                     later ALIASED as Hs (phase 2 A)
//   As : 128 x 36  @ 21120  (4608)  — emb staging (phase 1 A, k 128..255)
// strides 132 and 36 are ==4 (mod 32) -> conflict-free mma frag reads.

#define WS_S 132
#define AH_S 132
#define AS_S 36
#define SMEM_FLOATS (4224 + 16896 + 4608)   // 25728 floats = 102912 B

__global__ void __launch_bounds__(256, 2) k_mega(
    const float* __restrict__ emb,
    const int*   __restrict__ mask,
    const float* __restrict__ W1,   // [256,128]
    const float* __restrict__ b1,
    const float* __restrict__ W2,   // [128,128]
    const float* __restrict__ b2,
    float* __restrict__ out)
{
    extern __shared__ float sm[];
    float* Ws = sm;            // [32][WS_S]
    float* AH = sm + 4224;     // [128][AH_S]  (gather A / Hs alias)
    float* As = sm + 21120;    // [128][AS_S]

    int t = threadIdx.x;
    int lane = t & 31, wid = t >> 5;
    int gid = lane >> 2, tig = lane & 3;
    int warp_m = wid & 3, warp_n = wid >> 2;
    size_t rowbase = (size_t)blockIdx.x * 128;

    // ---- phase 0: gather neighbor rows for this tile, write tf32 into AH ----
    // warp w owns local rows w*16 .. w*16+15
    {
        for (int i = 0; i < 16; i++) {
            int rl = wid * 16 + i;
            size_t r = rowbase + rl;
            int b = (int)(r / NN), n = (int)(r % NN);
            int deg = min(g_cur[n], DPAD);
            const int* cols = g_colbuf + n * DPAD;
            const float4* eb = (const float4*)(emb + (size_t)b * NN * HH);
            float4 a4 = make_float4(0.f, 0.f, 0.f, 0.f);
            int j = 0;
            for (; j + 4 <= deg; j += 4) {
                int c0 = cols[j], c1 = cols[j + 1], c2 = cols[j + 2], c3 = cols[j + 3];
                float4 v0 = eb[c0 * 32 + lane];
                float4 v1 = eb[c1 * 32 + lane];
                float4 v2 = eb[c2 * 32 + lane];
                float4 v3 = eb[c3 * 32 + lane];
                a4.x += (v0.x + v1.x) + (v2.x + v3.x);
                a4.y += (v0.y + v1.y) + (v2.y + v3.y);
                a4.z += (v0.z + v1.z) + (v2.z + v3.z);
                a4.w += (v0.w + v1.w) + (v2.w + v3.w);
            }
            for (; j < deg; j++) {
                float4 v = eb[cols[j] * 32 + lane];
                a4.x += v.x; a4.y += v.y; a4.z += v.z; a4.w += v.w;
            }
            float* p = &AH[rl * AH_S + lane * 4];
            p[0] = __uint_as_float(f2tf32(a4.x));
            p[1] = __uint_as_float(f2tf32(a4.y));
            p[2] = __uint_as_float(f2tf32(a4.z));
            p[3] = __uint_as_float(f2tf32(a4.w));
        }
    }
    __syncthreads();

    float acc[2][8][4];
    #pragma unroll
    for (int mt = 0; mt < 2; mt++)
        #pragma unroll
        for (int nt = 0; nt < 8; nt++)
            #pragma unroll
            for (int i = 0; i < 4; i++) acc[mt][nt][i] = 0.f;

    // ---- phase 1a: neighbor @ W1[0:128], A frags straight from AH ----
    for (int kc = 0; kc < 4; ++kc) {
        if (kc > 0) __syncthreads();
        #pragma unroll
        for (int j = 0; j < 4; j++) {
            int idx = t + 256 * j;
            int kk = idx >> 5, cq = idx & 31;
            float4 v = *(const float4*)(W1 + (size_t)(kc * 32 + kk) * 128 + cq * 4);
            float* p = &Ws[kk * WS_S + cq * 4];
            p[0] = __uint_as_float(f2tf32(v.x));
            p[1] = __uint_as_float(f2tf32(v.y));
            p[2] = __uint_as_float(f2tf32(v.z));
            p[3] = __uint_as_float(f2tf32(v.w));
        }
        __syncthreads();
        #pragma unroll
        for (int ks = 0; ks < 4; ks++) {
            int k0 = ks * 8;
            int ka = kc * 32 + k0;          // column in AH
            uint32_t bfr[8][2];
            #pragma unroll
            for (int nt = 0; nt < 8; nt++) {
                int cb = warp_n * 64 + nt * 8 + gid;
                bfr[nt][0] = __float_as_uint(Ws[(k0 + tig) * WS_S + cb]);
                bfr[nt][1] = __float_as_uint(Ws[(k0 + tig + 4) * WS_S + cb]);
            }
            #pragma unroll
            for (int mt = 0; mt < 2; mt++) {
                int rb = warp_m * 32 + mt * 16;
                uint32_t a0 = __float_as_uint(AH[(rb + gid) * AH_S + ka + tig]);
                uint32_t a1 = __float_as_uint(AH[(rb + gid + 8) * AH_S + ka + tig]);
                uint32_t a2 = __float_as_uint(AH[(rb + gid) * AH_S + ka + tig + 4]);
                uint32_t a3 = __float_as_uint(AH[(rb + gid + 8) * AH_S + ka + tig + 4]);
                #pragma unroll
                for (int nt = 0; nt < 8; nt++)
                    mma_tf32(acc[mt][nt], a0, a1, a2, a3, bfr[nt][0], bfr[nt][1]);
            }
        }
    }

    // ---- phase 1b: emb @ W1[128:256], stage emb chunks into As ----
    for (int kc = 4; kc < 8; ++kc) {
        __syncthreads();
        int kof = (kc & 3) * 32;
        #pragma unroll
        for (int j = 0; j < 4; j++) {
            int idx = t + 256 * j;
            int row = idx >> 3, kq = idx & 7;
            float4 v = *(const float4*)(emb + (rowbase + row) * 128 + kof + kq * 4);
            float* p = &As[row * AS_S + kq * 4];
            p[0] = __uint_as_float(f2tf32(v.x));
            p[1] = __uint_as_float(f2tf32(v.y));
            p[2] = __uint_as_float(f2tf32(v.z));
            p[3] = __uint_as_float(f2tf32(v.w));
        }
        #pragma unroll
        for (int j = 0; j < 4; j++) {
            int idx = t + 256 * j;
            int kk = idx >> 5, cq = idx & 31;
            float4 v = *(const float4*)(W1 + (size_t)(kc * 32 + kk) * 128 + cq * 4);
            float* p = &Ws[kk * WS_S + cq * 4];
            p[0] = __uint_as_float(f2tf32(v.x));
            p[1] = __uint_as_float(f2tf32(v.y));
            p[2] = __uint_as_float(f2tf32(v.z));
            p[3] = __uint_as_float(f2tf32(v.w));
        }
        __syncthreads();
        #pragma unroll
        for (int ks = 0; ks < 4; ks++) {
            int k0 = ks * 8;
            uint32_t bfr[8][2];
            #pragma unroll
            for (int nt = 0; nt < 8; nt++) {
                int cb = warp_n * 64 + nt * 8 + gid;
                bfr[nt][0] = __float_as_uint(Ws[(k0 + tig) * WS_S + cb]);
                bfr[nt][1] = __float_as_uint(Ws[(k0 + tig + 4) * WS_S + cb]);
            }
            #pragma unroll
            for (int mt = 0; mt < 2; mt++) {
                int rb = warp_m * 32 + mt * 16;
                uint32_t a0 = __float_as_uint(As[(rb + gid) * AS_S + k0 + tig]);
                uint32_t a1 = __float_as_uint(As[(rb + gid + 8) * AS_S + k0 + tig]);
                uint32_t a2 = __float_as_uint(As[(rb + gid) * AS_S + k0 + tig + 4]);
                uint32_t a3 = __float_as_uint(As[(rb + gid + 8) * AS_S + k0 + tig + 4]);
                #pragma unroll
                for (int nt = 0; nt < 8; nt++)
                    mma_tf32(acc[mt][nt], a0, a1, a2, a3, bfr[nt][0], bfr[nt][1]);
            }
        }
    }
    __syncthreads();   // all AH reads done before Hs overwrite

    // ---- epilogue 1: h = relu(acc + b1) -> Hs (= AH alias, tf32); reset acc ----
    float* Hs = AH;
    #pragma unroll
    for (int mt = 0; mt < 2; mt++) {
        #pragma unroll
        for (int half = 0; half < 2; half++) {
            int r = warp_m * 32 + mt * 16 + gid + half * 8;
            #pragma unroll
            for (int nt = 0; nt < 8; nt++) {
                int c = warp_n * 64 + nt * 8 + tig * 2;
                float2 bv = *(const float2*)(b1 + c);
                float hx = fmaxf(acc[mt][nt][half * 2 + 0] + bv.x, 0.f);
                float hy = fmaxf(acc[mt][nt][half * 2 + 1] + bv.y, 0.f);
                Hs[r * AH_S + c]     = __uint_as_float(f2tf32(hx));
                Hs[r * AH_S + c + 1] = __uint_as_float(f2tf32(hy));
            }
        }
    }
    #pragma unroll
    for (int mt = 0; mt < 2; mt++)
        #pragma unroll
        for (int nt = 0; nt < 8; nt++)
            #pragma unroll
            for (int i = 0; i < 4; i++) acc[mt][nt][i] = 0.f;

    // ---- phase 2: h @ W2, K = 128 ----
    for (int kc = 0; kc < 4; ++kc) {
        __syncthreads();
        #pragma unroll
        for (int j = 0; j < 4; j++) {
            int idx = t + 256 * j;
            int kk = idx >> 5, cq = idx & 31;
            float4 v = *(const float4*)(W2 + (size_t)(kc * 32 + kk) * 128 + cq * 4);
            float* p = &Ws[kk * WS_S + cq * 4];
            p[0] = __uint_as_float(f2tf32(v.x));
            p[1] = __uint_as_float(f2tf32(v.y));
            p[2] = __uint_as_float(f2tf32(v.z));
            p[3] = __uint_as_float(f2tf32(v.w));
        }
        __syncthreads();
        #pragma unroll
        for (int ks = 0; ks < 4; ks++) {
            int k0 = kc * 32 + ks * 8;
            uint32_t bfr[8][2];
            #pragma unroll
            for (int nt = 0; nt < 8; nt++) {
                int cb = warp_n * 64 + nt * 8 + gid;
                bfr[nt][0] = __float_as_uint(Ws[(ks * 8 + tig) * WS_S + cb]);
                bfr[nt][1] = __float_as_uint(Ws[(ks * 8 + tig + 4) * WS_S + cb]);
            }
            #pragma unroll
            for (int mt = 0; mt < 2; mt++) {
                int rb = warp_m * 32 + mt * 16;
                uint32_t a0 = __float_as_uint(Hs[(rb + gid) * AH_S + k0 + tig]);
                uint32_t a1 = __float_as_uint(Hs[(rb + gid + 8) * AH_S + k0 + tig]);
                uint32_t a2 = __float_as_uint(Hs[(rb + gid) * AH_S + k0 + tig + 4]);
                uint32_t a3 = __float_as_uint(Hs[(rb + gid + 8) * AH_S + k0 + tig + 4]);
                #pragma unroll
                for (int nt = 0; nt < 8; nt++)
                    mma_tf32(acc[mt][nt], a0, a1, a2, a3, bfr[nt][0], bfr[nt][1]);
            }
        }
    }

    // ---- epilogue 2: bias + mask select ----
    #pragma unroll
    for (int mt = 0; mt < 2; mt++) {
        #pragma unroll
        for (int half = 0; half < 2; half++) {
            size_t r = rowbase + warp_m * 32 + mt * 16 + gid + half * 8;
            int m = mask[r];
            #pragma unroll
            for (int nt = 0; nt < 8; nt++) {
                int c = warp_n * 64 + nt * 8 + tig * 2;
                float2 o;
                if (m) {
                    float2 bv = *(const float2*)(b2 + c);
                    o.x = acc[mt][nt][half * 2 + 0] + bv.x;
                    o.y = acc[mt][nt][half * 2 + 1] + bv.y;
                } else {
                    o = *(const float2*)(emb + r * 128 + c);
                }
                *(float2*)(out + r * 128 + c) = o;
            }
        }
    }
}

// ---------------- launch ----------------

extern "C" void kernel_launch(void* const* d_in, const int* in_sizes, int n_in,
                              void* d_out, int out_size) {
    const float* emb  = (const float*)d_in[0];
    const int*   mask = (const int*)d_in[1];
    const int*   eidx = (const int*)d_in[2];
    const float* W1   = (const float*)d_in[3];
    const float* b1   = (const float*)d_in[4];
    const float* W2   = (const float*)d_in[5];
    const float* b2   = (const float*)d_in[6];
    const int* src = eidx;
    const int* dst = eidx + EE;
    float* out = (float*)d_out;

    cudaFuncSetAttribute(k_mega, cudaFuncAttributeMaxDynamicSharedMemorySize,
                         SMEM_FLOATS * 4);

    k_zero<<<(NN + 255) / 256, 256>>>();
    k_fill<<<(EE + 255) / 256, 256>>>(src, dst);
    k_mega<<<MM / 128, 256, SMEM_FLOATS * 4>>>(emb, mask, W1, b1, W2, b2, out);
}

// round 6
// speedup vs baseline: 1.3862x; 1.3862x over previous
#include <cuda_runtime.h>
#include <cstdint>

#define BB 16
#define NN 10000
#define HH 128
#define EE 320000
#define MM (BB * NN)   // 160000 rows
#define DPAD 128       // padded max degree (mean 32, 11+ sigma headroom)

// Scratch (static device allocations are the sanctioned workaround)
__device__ float g_neighbor[(size_t)MM * HH];   // 82 MB
__device__ int   g_cur[NN];
__device__ int   g_colbuf[NN * DPAD];           // 5.1 MB padded buckets

// ---------------- helpers ----------------

__device__ __forceinline__ uint32_t f2tf32(float x) {
    uint32_t u;
    asm("cvt.rna.tf32.f32 %0, %1;" : "=r"(u) : "f"(x));
    return u;
}

__device__ __forceinline__ void mma_tf32(float* d, uint32_t a0, uint32_t a1,
                                         uint32_t a2, uint32_t a3,
                                         uint32_t b0, uint32_t b1) {
    asm volatile(
        "mma.sync.aligned.m16n8k8.row.col.f32.tf32.tf32.f32 "
        "{%0,%1,%2,%3}, {%4,%5,%6,%7}, {%8,%9}, {%0,%1,%2,%3};"
        : "+f"(d[0]), "+f"(d[1]), "+f"(d[2]), "+f"(d[3])
        : "r"(a0), "r"(a1), "r"(a2), "r"(a3), "r"(b0), "r"(b1));
}

// ---------------- bucket build (no hist/scan) ----------------

__global__ void k_zero() {
    int i = blockIdx.x * blockDim.x + threadIdx.x;
    if (i < NN) g_cur[i] = 0;
}

__global__ void k_fill(const int* __restrict__ src, const int* __restrict__ dst) {
    int e = blockIdx.x * blockDim.x + threadIdx.x;
    if (e < EE) {
        int d = dst[e];
        int p = atomicAdd(&g_cur[d], 1);
        if (p < DPAD) g_colbuf[d * DPAD + p] = src[e];
    }
}

// ---------------- Gather (segment sum), standalone for high occupancy --------
// one warp per (b, node); 16 consecutive warps share node n (col-list reuse)

__global__ void __launch_bounds__(256) k_gather(const float* __restrict__ emb) {
    int wg   = (blockIdx.x * blockDim.x + threadIdx.x) >> 5;  // 0..MM-1
    int lane = threadIdx.x & 31;
    if (wg >= MM) return;
    int n = wg >> 4;
    int b = wg & 15;
    int deg = min(g_cur[n], DPAD);
    const int* cols = g_colbuf + n * DPAD;
    const float4* eb = (const float4*)(emb + (size_t)b * NN * HH);
    float4 acc = make_float4(0.f, 0.f, 0.f, 0.f);
    int i = 0;
    for (; i + 4 <= deg; i += 4) {
        int c0 = cols[i], c1 = cols[i + 1], c2 = cols[i + 2], c3 = cols[i + 3];
        float4 v0 = eb[c0 * 32 + lane];
        float4 v1 = eb[c1 * 32 + lane];
        float4 v2 = eb[c2 * 32 + lane];
        float4 v3 = eb[c3 * 32 + lane];
        acc.x += (v0.x + v1.x) + (v2.x + v3.x);
        acc.y += (v0.y + v1.y) + (v2.y + v3.y);
        acc.z += (v0.z + v1.z) + (v2.z + v3.z);
        acc.w += (v0.w + v1.w) + (v2.w + v3.w);
    }
    for (; i < deg; i++) {
        float4 v = eb[cols[i] * 32 + lane];
        acc.x += v.x; acc.y += v.y; acc.z += v.z; acc.w += v.w;
    }
    float4* op = (float4*)g_neighbor + ((size_t)(b * NN + n)) * 32 + lane;
    *op = acc;
}

// ---------------- Fused MLP: out = mask ? (relu([nb|emb]@W1+b1)@W2+b2) : emb ----
// Block: 128x128 tile, 256 threads = 8 warps (4m x 2n), warp tile 32x64.
// Dynamic smem (floats):
//   Ws: 32 x 136  @ 0      (4352)  — weight chunk (tf32)
//       stride 136 == 8 (mod 32) -> B-frag bank = 8*tig+gid : BIJECTIVE, no conflicts
//   As: 128 x 36  @ 4352   (4608)  — phase-1 A chunk;  bank = 4*gid+tig : bijective
//   Hs: 128 x 132 @ 4352   (16896) — phase-2 h tile (aliases As); same A pattern

#define WS_S 136
#define AS_S 36
#define HS_S 132
#define SMEM_FLOATS (4352 + 16896)   // 21248 floats = 84992 B -> 2 CTAs/SM

__global__ void __launch_bounds__(256, 2) k_fused(
    const float* __restrict__ emb,
    const int*   __restrict__ mask,
    const float* __restrict__ W1,   // [256,128]
    const float* __restrict__ b1,
    const float* __restrict__ W2,   // [128,128]
    const float* __restrict__ b2,
    float* __restrict__ out)
{
    extern __shared__ float sm[];
    float* Ws = sm;           // [32][WS_S]
    float* As = sm + 4352;    // [128][AS_S]
    float* Hs = sm + 4352;    // [128][HS_S] (aliases As)

    int t = threadIdx.x;
    int lane = t & 31, wid = t >> 5;
    int gid = lane >> 2, tig = lane & 3;
    int warp_m = wid & 3, warp_n = wid >> 2;
    size_t rowbase = (size_t)blockIdx.x * 128;

    float acc[2][8][4];
    #pragma unroll
    for (int mt = 0; mt < 2; mt++)
        #pragma unroll
        for (int nt = 0; nt < 8; nt++)
            #pragma unroll
            for (int i = 0; i < 4; i++) acc[mt][nt][i] = 0.f;

    // ---- phase 1: [neighbor | emb] @ W1, K = 256 ----
    for (int kc = 0; kc < 8; ++kc) {
        const float* A = (kc < 4) ? (const float*)g_neighbor : emb;
        int kof = (kc & 3) * 32;
        #pragma unroll
        for (int j = 0; j < 4; j++) {
            int idx = t + 256 * j;
            int row = idx >> 3, kq = idx & 7;
            float4 v = *(const float4*)(A + (rowbase + row) * 128 + kof + kq * 4);
            float* p = &As[row * AS_S + kq * 4];
            p[0] = __uint_as_float(f2tf32(v.x));
            p[1] = __uint_as_float(f2tf32(v.y));
            p[2] = __uint_as_float(f2tf32(v.z));
            p[3] = __uint_as_float(f2tf32(v.w));
        }
        #pragma unroll
        for (int j = 0; j < 4; j++) {
            int idx = t + 256 * j;
            int kk = idx >> 5, cq = idx & 31;
            float4 v = *(const float4*)(W1 + (size_t)(kc * 32 + kk) * 128 + cq * 4);
            float* p = &Ws[kk * WS_S + cq * 4];
            p[0] = __uint_as_float(f2tf32(v.x));
            p[1] = __uint_as_float(f2tf32(v.y));
            p[2] = __uint_as_float(f2tf32(v.z));
            p[3] = __uint_as_float(f2tf32(v.w));
        }
        __syncthreads();
        #pragma unroll
        for (int ks = 0; ks < 4; ks++) {
            int k0 = ks * 8;
            uint32_t bfr[8][2];
            #pragma unroll
            for (int nt = 0; nt < 8; nt++) {
                int cb = warp_n * 64 + nt * 8 + gid;
                bfr[nt][0] = __float_as_uint(Ws[(k0 + tig) * WS_S + cb]);
                bfr[nt][1] = __float_as_uint(Ws[(k0 + tig + 4) * WS_S + cb]);
            }
            #pragma unroll
            for (int mt = 0; mt < 2; mt++) {
                int rb = warp_m * 32 + mt * 16;
                uint32_t a0 = __float_as_uint(As[(rb + gid) * AS_S + k0 + tig]);
                uint32_t a1 = __float_as_uint(As[(rb + gid + 8) * AS_S + k0 + tig]);
                uint32_t a2 = __float_as_uint(As[(rb + gid) * AS_S + k0 + tig + 4]);
                uint32_t a3 = __float_as_uint(As[(rb + gid + 8) * AS_S + k0 + tig + 4]);
                #pragma unroll
                for (int nt = 0; nt < 8; nt++)
                    mma_tf32(acc[mt][nt], a0, a1, a2, a3, bfr[nt][0], bfr[nt][1]);
            }
        }
        __syncthreads();
    }

    // ---- epilogue 1: h = relu(acc + b1) -> Hs (tf32), reset acc ----
    #pragma unroll
    for (int mt = 0; mt < 2; mt++) {
        #pragma unroll
        for (int half = 0; half < 2; half++) {
            int r = warp_m * 32 + mt * 16 + gid + half * 8;
            #pragma unroll
            for (int nt = 0; nt < 8; nt++) {
                int c = warp_n * 64 + nt * 8 + tig * 2;
                float2 bv = *(const float2*)(b1 + c);
                float hx = fmaxf(acc[mt][nt][half * 2 + 0] + bv.x, 0.f);
                float hy = fmaxf(acc[mt][nt][half * 2 + 1] + bv.y, 0.f);
                Hs[r * HS_S + c]     = __uint_as_float(f2tf32(hx));
                Hs[r * HS_S + c + 1] = __uint_as_float(f2tf32(hy));
            }
        }
    }
    #pragma unroll
    for (int mt = 0; mt < 2; mt++)
        #pragma unroll
        for (int nt = 0; nt < 8; nt++)
            #pragma unroll
            for (int i = 0; i < 4; i++) acc[mt][nt][i] = 0.f;

    // ---- phase 2: h @ W2, K = 128, A from Hs ----
    for (int kc = 0; kc < 4; ++kc) {
        __syncthreads();   // Hs fully written (kc=0) / Ws free (kc>0)
        #pragma unroll
        for (int j = 0; j < 4; j++) {
            int idx = t + 256 * j;
            int kk = idx >> 5, cq = idx & 31;
            float4 v = *(const float4*)(W2 + (size_t)(kc * 32 + kk) * 128 + cq * 4);
            float* p = &Ws[kk * WS_S + cq * 4];
            p[0] = __uint_as_float(f2tf32(v.x));
            p[1] = __uint_as_float(f2tf32(v.y));
            p[2] = __uint_as_float(f2tf32(v.z));
            p[3] = __uint_as_float(f2tf32(v.w));
        }
        __syncthreads();
        #pragma unroll
        for (int ks = 0; ks < 4; ks++) {
            int k0 = kc * 32 + ks * 8;
            uint32_t bfr[8][2];
            #pragma unroll
            for (int nt = 0; nt < 8; nt++) {
                int cb = warp_n * 64 + nt * 8 + gid;
                bfr[nt][0] = __float_as_uint(Ws[(ks * 8 + tig) * WS_S + cb]);
                bfr[nt][1] = __float_as_uint(Ws[(ks * 8 + tig + 4) * WS_S + cb]);
            }
            #pragma unroll
            for (int mt = 0; mt < 2; mt++) {
                int rb = warp_m * 32 + mt * 16;
                uint32_t a0 = __float_as_uint(Hs[(rb + gid) * HS_S + k0 + tig]);
                uint32_t a1 = __float_as_uint(Hs[(rb + gid + 8) * HS_S + k0 + tig]);
                uint32_t a2 = __float_as_uint(Hs[(rb + gid) * HS_S + k0 + tig + 4]);
                uint32_t a3 = __float_as_uint(Hs[(rb + gid + 8) * HS_S + k0 + tig + 4]);
                #pragma unroll
                for (int nt = 0; nt < 8; nt++)
                    mma_tf32(acc[mt][nt], a0, a1, a2, a3, bfr[nt][0], bfr[nt][1]);
            }
        }
    }

    // ---- epilogue 2: bias + mask select ----
    #pragma unroll
    for (int mt = 0; mt < 2; mt++) {
        #pragma unroll
        for (int half = 0; half < 2; half++) {
            size_t r = rowbase + warp_m * 32 + mt * 16 + gid + half * 8;
            int m = mask[r];
            #pragma unroll
            for (int nt = 0; nt < 8; nt++) {
                int c = warp_n * 64 + nt * 8 + tig * 2;
                float2 o;
                if (m) {
                    float2 bv = *(const float2*)(b2 + c);
                    o.x = acc[mt][nt][half * 2 + 0] + bv.x;
                    o.y = acc[mt][nt][half * 2 + 1] + bv.y;
                } else {
                    o = *(const float2*)(emb + r * 128 + c);
                }
                *(float2*)(out + r * 128 + c) = o;
            }
        }
    }
}

// ---------------- launch ----------------

extern "C" void kernel_launch(void* const* d_in, const int* in_sizes, int n_in,
                              void* d_out, int out_size) {
    const float* emb  = (const float*)d_in[0];
    const int*   mask = (const int*)d_in[1];
    const int*   eidx = (const int*)d_in[2];
    const float* W1   = (const float*)d_in[3];
    const float* b1   = (const float*)d_in[4];
    const float* W2   = (const float*)d_in[5];
    const float* b2   = (const float*)d_in[6];
    const int* src = eidx;
    const int* dst = eidx + EE;
    float* out = (float*)d_out;

    cudaFuncSetAttribute(k_fused, cudaFuncAttributeMaxDynamicSharedMemorySize,
                         SMEM_FLOATS * 4);

    k_zero<<<(NN + 255) / 256, 256>>>();
    k_fill<<<(EE + 255) / 256, 256>>>(src, dst);
    k_gather<<<(MM * 32 + 255) / 256, 256>>>(emb);
    k_fused<<<MM / 128, 256, SMEM_FLOATS * 4>>>(emb, mask, W1, b1, W2, b2, out);
}